// round 2
// baseline (speedup 1.0000x reference)
#include <cuda_runtime.h>
#include <math.h>

#define T   4096
#define S   256
#define G   32       // DP CTAs: one warp per state row, 8 rows/CTA
#define NB  32       // backtrace chunks
#define CH  128      // steps per chunk (NB*CH == T)

// ---- device scratch (no cudaMalloc allowed) ----
__device__ unsigned long long g_v[2][S];   // (tag<<32 | f32 bits), parity double-buffered
__device__ int g_bp[T * S];                // backpointers
__device__ int g_link[NB][S];              // composed chunk maps

__device__ __forceinline__ void ld_acq_2u64(const unsigned long long* p,
                                            unsigned long long& a, unsigned long long& b) {
    asm volatile("ld.acquire.gpu.global.v2.u64 {%0,%1},[%2];"
                 : "=l"(a), "=l"(b) : "l"(p) : "memory");
}
__device__ __forceinline__ void st_rel_u64(unsigned long long* p, unsigned long long v) {
    asm volatile("st.release.gpu.global.u64 [%0],%1;" :: "l"(p), "l"(v) : "memory");
}

__global__ void sv_reset() {
    int i = threadIdx.x;               // 256 threads
    g_v[0][i] = ~0ULL;                 // tag = 0xFFFFFFFF (never matches t < 4096)
    g_v[1][i] = ~0ULL;
}

__global__ __launch_bounds__(256, 1)
void sv_dp(const float* __restrict__ pot, float* __restrict__ out) {
    const int tid  = threadIdx.x;
    const int w    = tid >> 5;
    const int lane = tid & 31;
    const int s    = (int)blockIdx.x * 8 + w;     // the state row this warp owns
    float* vout = out + T;                        // v[t*S + s]

    // step 0: v0 = pot[0,0,:]
    if (blockIdx.x == 0) vout[tid] = pot[tid];
    if (lane == 0) {
        float v0 = pot[s];
        st_rel_u64(&g_v[0][s], (unsigned long long)__float_as_uint(v0));  // tag 0
    }

    const float* prow = pot + (size_t)s * S;
    const int c0 = 4 * lane;            // cols c0..c0+3
    const int c1 = 128 + 4 * lane;      // cols c1..c1+3

    // prefetch pot for t = 1
    float4 pA = *(const float4*)(prow + (size_t)S * S + c0);
    float4 pB = *(const float4*)(prow + (size_t)S * S + c1);

    for (int t = 1; t < T; ++t) {
        // issue prefetch for t+1 (lands while we spin/compute)
        float4 nA = make_float4(0.f, 0.f, 0.f, 0.f), nB = nA;
        if (t + 1 < T) {
            nA = *(const float4*)(prow + (size_t)(t + 1) * S * S + c0);
            nB = *(const float4*)(prow + (size_t)(t + 1) * S * S + c1);
        }

        // poll v_{t-1}: value words carry their own tag
        const unsigned tg = (unsigned)(t - 1);
        const unsigned long long* vb = g_v[(t - 1) & 1];
        unsigned long long a0, a1, a2, a3, b0, b1, b2, b3;
        for (;;) {
            ld_acq_2u64(vb + c0,     a0, a1);
            ld_acq_2u64(vb + c0 + 2, a2, a3);
            ld_acq_2u64(vb + c1,     b0, b1);
            ld_acq_2u64(vb + c1 + 2, b2, b3);
            if ((((unsigned)(a0 >> 32) == tg) & ((unsigned)(a1 >> 32) == tg) &
                 ((unsigned)(a2 >> 32) == tg) & ((unsigned)(a3 >> 32) == tg) &
                 ((unsigned)(b0 >> 32) == tg) & ((unsigned)(b1 >> 32) == tg) &
                 ((unsigned)(b2 >> 32) == tg) & ((unsigned)(b3 >> 32) == tg))) break;
        }

        float sc[8];
        sc[0] = __uint_as_float((unsigned)a0) + pA.x;
        sc[1] = __uint_as_float((unsigned)a1) + pA.y;
        sc[2] = __uint_as_float((unsigned)a2) + pA.z;
        sc[3] = __uint_as_float((unsigned)a3) + pA.w;
        sc[4] = __uint_as_float((unsigned)b0) + pB.x;
        sc[5] = __uint_as_float((unsigned)b1) + pB.y;
        sc[6] = __uint_as_float((unsigned)b2) + pB.z;
        sc[7] = __uint_as_float((unsigned)b3) + pB.w;

        // local argmax (ascending col order -> first-index tie break)
        float m = sc[0]; int mi = c0;
        #pragma unroll
        for (int k = 1; k < 8; ++k) {
            int c = (k < 4) ? (c0 + k) : (c1 + k - 4);
            if (sc[k] > m) { m = sc[k]; mi = c; }
        }
        #pragma unroll
        for (int o = 16; o; o >>= 1) {
            float om = __shfl_xor_sync(0xffffffffu, m, o);
            int   oi = __shfl_xor_sync(0xffffffffu, mi, o);
            if (om > m || (om == m && oi < mi)) { m = om; mi = oi; }
        }

        float e = 0.f;
        #pragma unroll
        for (int k = 0; k < 8; ++k) e += __expf(sc[k] - m);
        #pragma unroll
        for (int o = 16; o; o >>= 1) e += __shfl_xor_sync(0xffffffffu, e, o);

        if (lane == 0) {
            float v = m + __logf(e);
            vout[(size_t)t * S + s] = v;
            g_bp[t * S + s] = mi;
            st_rel_u64(&g_v[t & 1][s],
                       ((unsigned long long)(unsigned)t << 32) |
                       (unsigned long long)__float_as_uint(v));
        }
        pA = nA; pB = nB;
    }
}

// compose each chunk's backpointer map: link[b][e] = path[b*CH-1] given path[b*CH+CH-1]=e
__global__ void sv_link() {
    int b = blockIdx.x;
    if (b == 0) return;
    int cur = threadIdx.x;
    int tlo = b * CH;
    for (int t = tlo + CH - 2; t >= tlo - 1; --t)
        cur = g_bp[(t + 1) * S + cur];
    g_link[b][threadIdx.x] = cur;
}

__global__ void sv_back(float* __restrict__ out) {
    __shared__ float sm[8];
    __shared__ int   si[8];
    __shared__ int   sE[NB];
    const int tid = threadIdx.x, lane = tid & 31;

    // argmax over v[T-1, :]
    const float* vlast = out + T + (size_t)(T - 1) * S;
    float m = vlast[tid]; int mi = tid;
    #pragma unroll
    for (int o = 16; o; o >>= 1) {
        float om = __shfl_xor_sync(0xffffffffu, m, o);
        int   oi = __shfl_xor_sync(0xffffffffu, mi, o);
        if (om > m || (om == m && oi < mi)) { m = om; mi = oi; }
    }
    if (lane == 0) { sm[tid >> 5] = m; si[tid >> 5] = mi; }
    __syncthreads();

    if (tid == 0) {
        m = sm[0]; mi = si[0];
        #pragma unroll
        for (int w = 1; w < 8; ++w)
            if (sm[w] > m || (sm[w] == m && si[w] < mi)) { m = sm[w]; mi = si[w]; }
        int e = mi;
        sE[NB - 1] = e;
        for (int b = NB - 1; b >= 1; --b) { e = g_link[b][e]; sE[b - 1] = e; }
    }
    __syncthreads();

    // replay each chunk in parallel
    if (tid < NB) {
        int b = tid;
        int cur = sE[b];
        out[b * CH + CH - 1] = (float)cur;
        for (int t = b * CH + CH - 2; t >= b * CH; --t) {
            cur = g_bp[(t + 1) * S + cur];
            out[t] = (float)cur;
        }
    }
}

extern "C" void kernel_launch(void* const* d_in, const int* in_sizes, int n_in,
                              void* d_out, int out_size) {
    const float* pot = (const float*)d_in[0];
    float* out = (float*)d_out;

    sv_reset<<<1, 256>>>();
    sv_dp<<<G, 256>>>(pot, out);
    sv_link<<<NB, 256>>>();
    sv_back<<<1, 256>>>(out);
}

// round 3
// speedup vs baseline: 2.7640x; 2.7640x over previous
#include <cuda_runtime.h>
#include <math.h>

#define T   4096
#define S   256
#define G   32       // DP CTAs: 8 warps each, one warp per state row
#define NB  64       // backtrace chunks
#define CH  64       // steps per chunk (NB*CH == T)

// ---- device scratch (no cudaMalloc allowed) ----
__device__ unsigned g_cnt;        // monotonic barrier counter (256 arrivals/step)
__device__ int g_bp[T * S];       // backpointers
__device__ int g_link[NB][S];     // composed chunk maps

__device__ __forceinline__ unsigned ld_acq(const unsigned* p) {
    unsigned v;
    asm volatile("ld.acquire.gpu.global.u32 %0, [%1];" : "=r"(v) : "l"(p) : "memory");
    return v;
}
__device__ __forceinline__ void red_rel_add1(unsigned* p) {
    asm volatile("red.release.gpu.global.add.u32 [%0], %1;" :: "l"(p), "r"(1u) : "memory");
}

__global__ void sv_reset() {
    if (threadIdx.x == 0) g_cnt = 0u;
}

__global__ __launch_bounds__(256, 1)
void sv_dp(const float* __restrict__ pot, float* __restrict__ out) {
    const int tid  = threadIdx.x;
    const int w    = tid >> 5;
    const int lane = tid & 31;
    const int s    = (int)blockIdx.x * 8 + w;   // state row owned by this warp
    float* vout = out + T;                      // v[t*S + s]

    // v row 0 of the output = pot[0,0,:]
    if (blockIdx.x == 0) vout[tid] = pot[tid];

    const float* prow = pot + (size_t)s * S;
    const int c0 = 4 * lane;          // columns c0..c0+3
    const int c1 = 128 + 4 * lane;    // columns c1..c1+3

    // prefetch pot for t = 1
    float4 pA = *(const float4*)(prow + (size_t)S * S + c0);
    float4 pB = *(const float4*)(prow + (size_t)S * S + c1);

    for (int t = 1; t < T; ++t) {
        // issue prefetch for t+1 (lands during the poll / compute)
        float4 nA, nB;
        if (t + 1 < T) {
            nA = *(const float4*)(prow + (size_t)(t + 1) * S * S + c0);
            nB = *(const float4*)(prow + (size_t)(t + 1) * S * S + c1);
        }

        // wait for all 256 rows of step t-1 (t==1 reads the input directly)
        if (t > 1) {
            const unsigned tgt = 256u * (unsigned)(t - 1);
            while (ld_acq(&g_cnt) < tgt) { }
        }

        // load v_{t-1} (L2; acquire above orders these)
        const float* vsrc = (t == 1) ? pot : (vout + (size_t)(t - 1) * S);
        float4 vA = __ldcg((const float4*)(vsrc + c0));
        float4 vB = __ldcg((const float4*)(vsrc + c1));

        float sc[8];
        sc[0] = vA.x + pA.x;  sc[1] = vA.y + pA.y;
        sc[2] = vA.z + pA.z;  sc[3] = vA.w + pA.w;
        sc[4] = vB.x + pB.x;  sc[5] = vB.y + pB.y;
        sc[6] = vB.z + pB.z;  sc[7] = vB.w + pB.w;

        // local (max, argmax) with first-index tie-break (ascending col order)
        float m = sc[0]; int mi = c0;
        #pragma unroll
        for (int k = 1; k < 8; ++k) {
            int c = (k < 4) ? (c0 + k) : (c1 + (k - 4));
            if (sc[k] > m) { m = sc[k]; mi = c; }
        }
        float d = 0.f;
        #pragma unroll
        for (int k = 0; k < 8; ++k) d += __expf(sc[k] - m);

        // single-pass online LSE + argmax across the warp
        #pragma unroll
        for (int o = 16; o; o >>= 1) {
            float om = __shfl_xor_sync(0xffffffffu, m, o);
            int   oi = __shfl_xor_sync(0xffffffffu, mi, o);
            float od = __shfl_xor_sync(0xffffffffu, d, o);
            if (om > m || (om == m && oi < mi)) {
                d = od + d * __expf(m - om);
                m = om; mi = oi;
            } else {
                d = d + od * __expf(om - m);
            }
        }

        if (lane == 0) {
            vout[(size_t)t * S + s] = m + __logf(d);
            g_bp[t * S + s] = mi;
            red_rel_add1(&g_cnt);        // release orders the stores above
        }
        pA = nA; pB = nB;
    }
}

// compose each chunk's backpointer map: link[b][e] = path[b*CH-1] given path[(b+1)*CH-1]=e
__global__ void sv_link() {
    int b = blockIdx.x;
    if (b == 0) return;
    int cur = threadIdx.x;
    int tlo = b * CH;
    for (int t = tlo + CH - 2; t >= tlo - 1; --t)
        cur = g_bp[(t + 1) * S + cur];
    g_link[b][threadIdx.x] = cur;
}

__global__ void sv_back(float* __restrict__ out) {
    __shared__ float sm[8];
    __shared__ int   si[8];
    __shared__ int   sE[NB];
    const int tid = threadIdx.x, lane = tid & 31;

    // argmax over v[T-1, :] (first max index)
    const float* vlast = out + T + (size_t)(T - 1) * S;
    float m = vlast[tid]; int mi = tid;
    #pragma unroll
    for (int o = 16; o; o >>= 1) {
        float om = __shfl_xor_sync(0xffffffffu, m, o);
        int   oi = __shfl_xor_sync(0xffffffffu, mi, o);
        if (om > m || (om == m && oi < mi)) { m = om; mi = oi; }
    }
    if (lane == 0) { sm[tid >> 5] = m; si[tid >> 5] = mi; }
    __syncthreads();

    if (tid == 0) {
        m = sm[0]; mi = si[0];
        #pragma unroll
        for (int w = 1; w < 8; ++w)
            if (sm[w] > m || (sm[w] == m && si[w] < mi)) { m = sm[w]; mi = si[w]; }
        int e = mi;
        sE[NB - 1] = e;
        for (int b = NB - 1; b >= 1; --b) { e = g_link[b][e]; sE[b - 1] = e; }
    }
    __syncthreads();

    // replay the chunks in parallel
    if (tid < NB) {
        int b = tid;
        int cur = sE[b];
        out[b * CH + CH - 1] = (float)cur;
        for (int t = b * CH + CH - 2; t >= b * CH; --t) {
            cur = g_bp[(t + 1) * S + cur];
            out[t] = (float)cur;
        }
    }
}

extern "C" void kernel_launch(void* const* d_in, const int* in_sizes, int n_in,
                              void* d_out, int out_size) {
    const float* pot = (const float*)d_in[0];
    float* out = (float*)d_out;

    sv_reset<<<1, 32>>>();
    sv_dp<<<G, 256>>>(pot, out);
    sv_link<<<NB, 256>>>();
    sv_back<<<1, 256>>>(out);
}

// round 4
// speedup vs baseline: 3.4720x; 1.2561x over previous
#include <cuda_runtime.h>
#include <math.h>

#define T   4096
#define S   256
#define G   128      // DP CTAs: 2 warps each, one warp per state row (<=148 SMs)
#define NB  64       // backtrace chunks
#define CH  64       // steps per chunk (NB*CH == T)

// ---- device scratch (no cudaMalloc allowed) ----
__device__ unsigned g_cnt;        // monotonic barrier counter (256 warp-arrivals/step)
__device__ int g_bp[T * S];       // backpointers
__device__ int g_link[NB][S];     // composed chunk maps

__device__ __forceinline__ unsigned ld_acq(const unsigned* p) {
    unsigned v;
    asm volatile("ld.acquire.gpu.global.u32 %0, [%1];" : "=r"(v) : "l"(p) : "memory");
    return v;
}
__device__ __forceinline__ void red_rel_add1(unsigned* p) {
    asm volatile("red.release.gpu.global.add.u32 [%0], %1;" :: "l"(p), "r"(1u) : "memory");
}

__global__ void sv_reset() {
    if (threadIdx.x == 0) g_cnt = 0u;
}

__global__ __launch_bounds__(64, 1)
void sv_dp(const float* __restrict__ pot, float* __restrict__ out) {
    const int tid  = threadIdx.x;
    const int w    = tid >> 5;                  // 0 or 1
    const int lane = tid & 31;
    const int s    = (int)blockIdx.x * 2 + w;   // state row owned by this warp
    float* vout = out + T;                      // v[t*S + s]

    // v row 0 of the output = pot[0,0,:]
    if (blockIdx.x == 0) {
        vout[tid]       = pot[tid];
        vout[tid + 64]  = pot[tid + 64];
        vout[tid + 128] = pot[tid + 128];
        vout[tid + 192] = pot[tid + 192];
    }

    const float* prow = pot + (size_t)s * S;
    const int c0 = 4 * lane;          // columns c0..c0+3
    const int c1 = 128 + 4 * lane;    // columns c1..c1+3

    // K-shift base: our own row's previous v (exact same LSE up to rounding)
    float K = pot[s];                 // v0[s]

    // prefetch pot for t = 1
    float4 pA = *(const float4*)(prow + (size_t)S * S + c0);
    float4 pB = *(const float4*)(prow + (size_t)S * S + c1);

    for (int t = 1; t < T; ++t) {
        // issue prefetch for t+1 (lands during the poll / compute)
        const size_t nxt = (size_t)((t + 1 < T) ? (t + 1) : t) * S * S;
        float4 nA = *(const float4*)(prow + nxt + c0);
        float4 nB = *(const float4*)(prow + nxt + c1);

        // wait for all 256 rows of step t-1 (t==1 reads the input directly)
        if (t > 1) {
            const unsigned tgt = 256u * (unsigned)(t - 1);
            while (ld_acq(&g_cnt) < tgt) { }
        }

        // load v_{t-1} (L2; acquire above orders these)
        const float* vsrc = (t == 1) ? pot : (vout + (size_t)(t - 1) * S);
        float4 vA = __ldcg((const float4*)(vsrc + c0));
        float4 vB = __ldcg((const float4*)(vsrc + c1));

        float sc[8];
        sc[0] = vA.x + pA.x;  sc[1] = vA.y + pA.y;
        sc[2] = vA.z + pA.z;  sc[3] = vA.w + pA.w;
        sc[4] = vB.x + pB.x;  sc[5] = vB.y + pB.y;
        sc[6] = vB.z + pB.z;  sc[7] = vB.w + pB.w;

        // exps start immediately (no max dependency thanks to K-shift)
        float e = __expf(sc[0] - K) + __expf(sc[1] - K) +
                  __expf(sc[2] - K) + __expf(sc[3] - K) +
                  __expf(sc[4] - K) + __expf(sc[5] - K) +
                  __expf(sc[6] - K) + __expf(sc[7] - K);

        // local (max, argmax), first-index tie-break (ascending col order)
        float m = sc[0]; int mi = c0;
        #pragma unroll
        for (int k = 1; k < 8; ++k) {
            int c = (k < 4) ? (c0 + k) : (c1 + (k - 4));
            if (sc[k] > m) { m = sc[k]; mi = c; }
        }

        // single 5-level tree: sum e, argmax (m, mi)
        #pragma unroll
        for (int o = 16; o; o >>= 1) {
            float oe = __shfl_xor_sync(0xffffffffu, e, o);
            float om = __shfl_xor_sync(0xffffffffu, m, o);
            int   oi = __shfl_xor_sync(0xffffffffu, mi, o);
            e += oe;
            if (om > m || (om == m && oi < mi)) { m = om; mi = oi; }
        }

        float v = K + __logf(e);      // all lanes compute (saves a broadcast)
        if (lane == 0) {
            vout[(size_t)t * S + s] = v;
            g_bp[t * S + s] = mi;
            red_rel_add1(&g_cnt);     // release orders the stores above
        }
        K = v;
        pA = nA; pB = nB;
    }
}

// compose each chunk's backpointer map: link[b][e] = path[b*CH-1] given path[(b+1)*CH-1]=e
__global__ void sv_link() {
    int b = blockIdx.x;
    if (b == 0) return;
    int cur = threadIdx.x;
    int tlo = b * CH;
    for (int t = tlo + CH - 2; t >= tlo - 1; --t)
        cur = g_bp[(t + 1) * S + cur];
    g_link[b][threadIdx.x] = cur;
}

__global__ void sv_back(float* __restrict__ out) {
    __shared__ float sm[8];
    __shared__ int   si[8];
    __shared__ int   sE[NB];
    const int tid = threadIdx.x, lane = tid & 31;

    // argmax over v[T-1, :] (first max index)
    const float* vlast = out + T + (size_t)(T - 1) * S;
    float m = vlast[tid]; int mi = tid;
    #pragma unroll
    for (int o = 16; o; o >>= 1) {
        float om = __shfl_xor_sync(0xffffffffu, m, o);
        int   oi = __shfl_xor_sync(0xffffffffu, mi, o);
        if (om > m || (om == m && oi < mi)) { m = om; mi = oi; }
    }
    if (lane == 0) { sm[tid >> 5] = m; si[tid >> 5] = mi; }
    __syncthreads();

    if (tid == 0) {
        m = sm[0]; mi = si[0];
        #pragma unroll
        for (int w = 1; w < 8; ++w)
            if (sm[w] > m || (sm[w] == m && si[w] < mi)) { m = sm[w]; mi = si[w]; }
        int e = mi;
        sE[NB - 1] = e;
        for (int b = NB - 1; b >= 1; --b) { e = g_link[b][e]; sE[b - 1] = e; }
    }
    __syncthreads();

    // replay the chunks in parallel
    if (tid < NB) {
        int b = tid;
        int cur = sE[b];
        out[b * CH + CH - 1] = (float)cur;
        for (int t = b * CH + CH - 2; t >= b * CH; --t) {
            cur = g_bp[(t + 1) * S + cur];
            out[t] = (float)cur;
        }
    }
}

extern "C" void kernel_launch(void* const* d_in, const int* in_sizes, int n_in,
                              void* d_out, int out_size) {
    const float* pot = (const float*)d_in[0];
    float* out = (float*)d_out;

    sv_reset<<<1, 32>>>();
    sv_dp<<<G, 64>>>(pot, out);
    sv_link<<<NB, 256>>>();
    sv_back<<<1, 256>>>(out);
}

// round 5
// speedup vs baseline: 3.4804x; 1.0024x over previous
#include <cuda_runtime.h>
#include <math.h>

#define T   4096
#define S   256
#define G   128      // DP CTAs: 2 warps each, one warp per state row (<=148 SMs)
#define NB  64       // backtrace chunks
#define CH  64       // steps per chunk (NB*CH == T)
#define NC  8        // striped barrier counters
#define CSTRIDE 128  // u32 stride between counters (512 B -> distinct L2 slices)

// ---- device scratch (no cudaMalloc allowed) ----
__device__ unsigned g_cnt8[NC * CSTRIDE];   // striped barrier counters
__device__ int g_bp[T * S];                 // backpointers
__device__ int g_link[NB][S];               // composed chunk maps

__device__ __forceinline__ unsigned ld_acq(const unsigned* p) {
    unsigned v;
    asm volatile("ld.acquire.gpu.global.u32 %0, [%1];" : "=r"(v) : "l"(p) : "memory");
    return v;
}
__device__ __forceinline__ void red_rel_add1(unsigned* p) {
    asm volatile("red.release.gpu.global.add.u32 [%0], %1;" :: "l"(p), "r"(1u) : "memory");
}

__global__ void sv_reset() {
    if (threadIdx.x < NC) g_cnt8[threadIdx.x * CSTRIDE] = 0u;
}

__global__ __launch_bounds__(64, 1)
void sv_dp(const float* __restrict__ pot, float* __restrict__ out) {
    const int tid  = threadIdx.x;
    const int w    = tid >> 5;                  // 0 or 1
    const int lane = tid & 31;
    const int s    = (int)blockIdx.x * 2 + w;   // state row owned by this warp
    float* vout = out + T;                      // v[t*S + s]

    // v row 0 of the output = pot[0,0,:]
    if (blockIdx.x == 0) {
        vout[tid]       = pot[tid];
        vout[tid + 64]  = pot[tid + 64];
        vout[tid + 128] = pot[tid + 128];
        vout[tid + 192] = pot[tid + 192];
    }

    unsigned* my_cnt   = &g_cnt8[(s & (NC - 1)) * CSTRIDE];
    const unsigned* poll_cnt = &g_cnt8[(lane & (NC - 1)) * CSTRIDE];

    const float* prow = pot + (size_t)s * S;
    const int c0 = 4 * lane;          // columns c0..c0+3
    const int c1 = 128 + 4 * lane;    // columns c1..c1+3

    // K-shift base: our own row's previous v (same LSE up to rounding)
    float K = pot[s];                 // v0[s]

    // prefetch pot for t = 1
    float4 pA = *(const float4*)(prow + (size_t)S * S + c0);
    float4 pB = *(const float4*)(prow + (size_t)S * S + c1);

    for (int t = 1; t < T; ++t) {
        // issue prefetch for t+1 (lands during the poll / compute)
        const size_t nxt = (size_t)((t + 1 < T) ? (t + 1) : t) * S * S;
        float4 nA = *(const float4*)(prow + nxt + c0);
        float4 nB = *(const float4*)(prow + nxt + c1);

        // wait for all 256 rows of step t-1 (each counter needs 32*(t-1))
        if (t > 1) {
            const unsigned tgt = 32u * (unsigned)(t - 1);
            for (;;) {
                unsigned cv = ld_acq(poll_cnt);
                if (__all_sync(0xffffffffu, cv >= tgt)) break;
            }
        }

        // load v_{t-1} (L2; barrier above orders these)
        const float* vsrc = (t == 1) ? pot : (vout + (size_t)(t - 1) * S);
        float4 vA = __ldcg((const float4*)(vsrc + c0));
        float4 vB = __ldcg((const float4*)(vsrc + c1));

        float sc[8];
        sc[0] = vA.x + pA.x;  sc[1] = vA.y + pA.y;
        sc[2] = vA.z + pA.z;  sc[3] = vA.w + pA.w;
        sc[4] = vB.x + pB.x;  sc[5] = vB.y + pB.y;
        sc[6] = vB.z + pB.z;  sc[7] = vB.w + pB.w;

        // exps start immediately (no max dependency thanks to K-shift)
        float e = __expf(sc[0] - K) + __expf(sc[1] - K) +
                  __expf(sc[2] - K) + __expf(sc[3] - K) +
                  __expf(sc[4] - K) + __expf(sc[5] - K) +
                  __expf(sc[6] - K) + __expf(sc[7] - K);

        // sum-only tree (1 shfl per level) -> publish ASAP
        #pragma unroll
        for (int o = 16; o; o >>= 1)
            e += __shfl_xor_sync(0xffffffffu, e, o);

        float v = K + __logf(e);
        if (lane == 0) {
            vout[(size_t)t * S + s] = v;
            red_rel_add1(my_cnt);     // release orders the store above
        }

        // ---- off the critical path: argmax -> backpointer ----
        float m = sc[0]; int mi = c0;
        #pragma unroll
        for (int k = 1; k < 8; ++k) {
            int c = (k < 4) ? (c0 + k) : (c1 + (k - 4));
            if (sc[k] > m) { m = sc[k]; mi = c; }
        }
        #pragma unroll
        for (int o = 16; o; o >>= 1) {
            float om = __shfl_xor_sync(0xffffffffu, m, o);
            int   oi = __shfl_xor_sync(0xffffffffu, mi, o);
            if (om > m || (om == m && oi < mi)) { m = om; mi = oi; }
        }
        if (lane == 0) g_bp[t * S + s] = mi;   // read only by later kernels

        K = v;
        pA = nA; pB = nB;
    }
}

// compose each chunk's backpointer map: link[b][e] = path[b*CH-1] given path[(b+1)*CH-1]=e
__global__ void sv_link() {
    int b = blockIdx.x;
    if (b == 0) return;
    int cur = threadIdx.x;
    int tlo = b * CH;
    for (int t = tlo + CH - 2; t >= tlo - 1; --t)
        cur = g_bp[(t + 1) * S + cur];
    g_link[b][threadIdx.x] = cur;
}

__global__ void sv_back(float* __restrict__ out) {
    __shared__ float sm[8];
    __shared__ int   si[8];
    __shared__ int   sE[NB];
    const int tid = threadIdx.x, lane = tid & 31;

    // argmax over v[T-1, :] (first max index)
    const float* vlast = out + T + (size_t)(T - 1) * S;
    float m = vlast[tid]; int mi = tid;
    #pragma unroll
    for (int o = 16; o; o >>= 1) {
        float om = __shfl_xor_sync(0xffffffffu, m, o);
        int   oi = __shfl_xor_sync(0xffffffffu, mi, o);
        if (om > m || (om == m && oi < mi)) { m = om; mi = oi; }
    }
    if (lane == 0) { sm[tid >> 5] = m; si[tid >> 5] = mi; }
    __syncthreads();

    if (tid == 0) {
        m = sm[0]; mi = si[0];
        #pragma unroll
        for (int w = 1; w < 8; ++w)
            if (sm[w] > m || (sm[w] == m && si[w] < mi)) { m = sm[w]; mi = si[w]; }
        int e = mi;
        sE[NB - 1] = e;
        for (int b = NB - 1; b >= 1; --b) { e = g_link[b][e]; sE[b - 1] = e; }
    }
    __syncthreads();

    // replay the chunks in parallel
    if (tid < NB) {
        int b = tid;
        int cur = sE[b];
        out[b * CH + CH - 1] = (float)cur;
        for (int t = b * CH + CH - 2; t >= b * CH; --t) {
            cur = g_bp[(t + 1) * S + cur];
            out[t] = (float)cur;
        }
    }
}

extern "C" void kernel_launch(void* const* d_in, const int* in_sizes, int n_in,
                              void* d_out, int out_size) {
    const float* pot = (const float*)d_in[0];
    float* out = (float*)d_out;

    sv_reset<<<1, 32>>>();
    sv_dp<<<G, 64>>>(pot, out);
    sv_link<<<NB, 256>>>();
    sv_back<<<1, 256>>>(out);
}

// round 6
// speedup vs baseline: 4.2568x; 1.2231x over previous
#include <cuda_runtime.h>
#include <math.h>
#include <cstdint>

#define T    4096
#define S    256
#define NCTA 8        // cluster size (portable max)
#define WPC  32       // warps per CTA -> NCTA*WPC == S rows
#define NB   64       // backtrace chunks
#define CH   64       // steps per chunk (NB*CH == T)

// ---- device scratch (no cudaMalloc allowed) ----
__device__ int g_bp[T * S];       // backpointers
__device__ int g_link[NB][S];     // composed chunk maps

__device__ __forceinline__ uint32_t smem_u32(const void* p) {
    uint32_t a;
    asm("{ .reg .u64 t; cvta.to.shared.u64 t, %1; cvt.u32.u64 %0, t; }"
        : "=r"(a) : "l"(p));
    return a;
}
__device__ __forceinline__ uint32_t ctarank() {
    uint32_t r;
    asm("mov.u32 %0, %%cluster_ctarank;" : "=r"(r));
    return r;
}

__global__ __launch_bounds__(1024, 1) __cluster_dims__(NCTA, 1, 1)
void sv_dp(const float* __restrict__ pot, float* __restrict__ out) {
    __shared__ float vbuf[2][S];      // double-buffered v, full copy per CTA

    const int tid  = threadIdx.x;
    const int w    = tid >> 5;
    const int lane = tid & 31;
    const uint32_t rank = ctarank();
    const int s    = (int)rank * WPC + w;       // state row owned by this warp
    float* vout = out + T;                      // v[t*S + s]

    // v0 = pot[0,0,:]: every CTA fills its local copy; CTA 0 also writes output
    if (tid < S) {
        vbuf[0][tid] = pot[tid];
        if (rank == 0) vout[tid] = pot[tid];
    }
    __syncthreads();

    const float* prow = pot + (size_t)s * S;
    const int c0 = 4 * lane;          // columns c0..c0+3
    const int c1 = 128 + 4 * lane;    // columns c1..c1+3

    // K-shift base: own row's previous v (kept in registers, all lanes)
    float K = pot[s];

    // smem addresses of our slot in each parity buffer
    const uint32_t slot0 = smem_u32(&vbuf[0][s]);
    const uint32_t slot1 = smem_u32(&vbuf[1][s]);

    // prefetch pot for t = 1
    float4 pA = *(const float4*)(prow + (size_t)S * S + c0);
    float4 pB = *(const float4*)(prow + (size_t)S * S + c1);

    for (int t = 1; t < T; ++t) {
        // issue prefetch for t+1 (lands during barrier/compute)
        const size_t nxt = (size_t)((t + 1 < T) ? (t + 1) : t) * S * S;
        float4 nA = *(const float4*)(prow + nxt + c0);
        float4 nB = *(const float4*)(prow + nxt + c1);

        // read v_{t-1} from LOCAL smem
        const float* vp = vbuf[(t - 1) & 1];
        float4 vA = *(const float4*)(vp + c0);
        float4 vB = *(const float4*)(vp + c1);

        float sc[8];
        sc[0] = vA.x + pA.x;  sc[1] = vA.y + pA.y;
        sc[2] = vA.z + pA.z;  sc[3] = vA.w + pA.w;
        sc[4] = vB.x + pB.x;  sc[5] = vB.y + pB.y;
        sc[6] = vB.z + pB.z;  sc[7] = vB.w + pB.w;

        // exps start immediately (K-shift: no max dependency)
        float e = __expf(sc[0] - K) + __expf(sc[1] - K) +
                  __expf(sc[2] - K) + __expf(sc[3] - K) +
                  __expf(sc[4] - K) + __expf(sc[5] - K) +
                  __expf(sc[6] - K) + __expf(sc[7] - K);

        // sum-only tree
        #pragma unroll
        for (int o = 16; o; o >>= 1)
            e += __shfl_xor_sync(0xffffffffu, e, o);

        float v = K + __logf(e);      // all lanes have v

        // publish v_t[s] into all 8 CTAs' smem (lanes 0..7, one rank each)
        const uint32_t dst = (t & 1) ? slot1 : slot0;
        if (lane < NCTA) {
            uint32_t rem;
            asm("mapa.shared::cluster.u32 %0, %1, %2;"
                : "=r"(rem) : "r"(dst), "r"(lane));
            asm volatile("st.shared::cluster.f32 [%0], %1;"
                         :: "r"(rem), "f"(v) : "memory");
        }
        asm volatile("barrier.cluster.arrive.aligned;" ::: "memory");

        // ---- off the critical path (between arrive and wait) ----
        if (lane == 0) vout[(size_t)t * S + s] = v;

        float m = sc[0]; int mi = c0;
        #pragma unroll
        for (int k = 1; k < 8; ++k) {
            int c = (k < 4) ? (c0 + k) : (c1 + (k - 4));
            if (sc[k] > m) { m = sc[k]; mi = c; }
        }
        #pragma unroll
        for (int o = 16; o; o >>= 1) {
            float om = __shfl_xor_sync(0xffffffffu, m, o);
            int   oi = __shfl_xor_sync(0xffffffffu, mi, o);
            if (om > m || (om == m && oi < mi)) { m = om; mi = oi; }
        }
        if (lane == 0) g_bp[t * S + s] = mi;   // read only by later kernels

        K = v;
        pA = nA; pB = nB;

        asm volatile("barrier.cluster.wait.aligned;" ::: "memory");
    }
}

// compose each chunk's backpointer map: link[b][e] = path[b*CH-1] given path[(b+1)*CH-1]=e
__global__ void sv_link() {
    int b = blockIdx.x;
    if (b == 0) return;
    int cur = threadIdx.x;
    int tlo = b * CH;
    for (int t = tlo + CH - 2; t >= tlo - 1; --t)
        cur = g_bp[(t + 1) * S + cur];
    g_link[b][threadIdx.x] = cur;
}

__global__ void sv_back(float* __restrict__ out) {
    __shared__ float sm[8];
    __shared__ int   si[8];
    __shared__ int   sE[NB];
    const int tid = threadIdx.x, lane = tid & 31;

    // argmax over v[T-1, :] (first max index)
    const float* vlast = out + T + (size_t)(T - 1) * S;
    float m = vlast[tid]; int mi = tid;
    #pragma unroll
    for (int o = 16; o; o >>= 1) {
        float om = __shfl_xor_sync(0xffffffffu, m, o);
        int   oi = __shfl_xor_sync(0xffffffffu, mi, o);
        if (om > m || (om == m && oi < mi)) { m = om; mi = oi; }
    }
    if (lane == 0) { sm[tid >> 5] = m; si[tid >> 5] = mi; }
    __syncthreads();

    if (tid == 0) {
        m = sm[0]; mi = si[0];
        #pragma unroll
        for (int w = 1; w < 8; ++w)
            if (sm[w] > m || (sm[w] == m && si[w] < mi)) { m = sm[w]; mi = si[w]; }
        int e = mi;
        sE[NB - 1] = e;
        for (int b = NB - 1; b >= 1; --b) { e = g_link[b][e]; sE[b - 1] = e; }
    }
    __syncthreads();

    // replay the chunks in parallel
    if (tid < NB) {
        int b = tid;
        int cur = sE[b];
        out[b * CH + CH - 1] = (float)cur;
        for (int t = b * CH + CH - 2; t >= b * CH; --t) {
            cur = g_bp[(t + 1) * S + cur];
            out[t] = (float)cur;
        }
    }
}

extern "C" void kernel_launch(void* const* d_in, const int* in_sizes, int n_in,
                              void* d_out, int out_size) {
    const float* pot = (const float*)d_in[0];
    float* out = (float*)d_out;

    sv_dp<<<NCTA, 1024>>>(pot, out);
    sv_link<<<NB, 256>>>();
    sv_back<<<1, 256>>>(out);
}

// round 7
// speedup vs baseline: 4.3567x; 1.0235x over previous
#include <cuda_runtime.h>
#include <math.h>
#include <cstdint>

#define T    4096
#define S    256
#define NCTA 8        // cluster size (portable max)
#define WPC  32       // warps per CTA -> NCTA*WPC == S rows
#define NB   64       // backtrace chunks
#define CH   64       // steps per chunk (NB*CH == T)

// ---- device scratch (no cudaMalloc allowed) ----
__device__ int g_bp[T * S];       // backpointers (filled by sv_bp post-pass)
__device__ int g_link[NB][S];     // composed chunk maps

__device__ __forceinline__ uint32_t smem_u32(const void* p) {
    uint32_t a;
    asm("{ .reg .u64 t; cvta.to.shared.u64 t, %1; cvt.u32.u64 %0, t; }"
        : "=r"(a) : "l"(p));
    return a;
}
__device__ __forceinline__ uint32_t ctarank() {
    uint32_t r;
    asm("mov.u32 %0, %%cluster_ctarank;" : "=r"(r));
    return r;
}

// ============ sequential DP: LSE only, no argmax ============
__global__ __launch_bounds__(1024, 1) __cluster_dims__(NCTA, 1, 1)
void sv_dp(const float* __restrict__ pot, float* __restrict__ out) {
    __shared__ float vbuf[2][S];      // double-buffered v, full copy per CTA

    const int tid  = threadIdx.x;
    const int w    = tid >> 5;
    const int lane = tid & 31;
    const uint32_t rank = ctarank();
    const int s    = (int)rank * WPC + w;       // state row owned by this warp
    float* vout = out + T;                      // v[t*S + s]

    // v0 = pot[0,0,:]: every CTA fills its local copy; CTA 0 also writes output
    if (tid < S) {
        vbuf[0][tid] = pot[tid];
        if (rank == 0) vout[tid] = pot[tid];
    }
    __syncthreads();

    const float* prow = pot + (size_t)s * S;
    const int c0 = 4 * lane;          // columns c0..c0+3
    const int c1 = 128 + 4 * lane;    // columns c1..c1+3

    float K = pot[s];                 // K-shift base (own previous v)

    const uint32_t slot0 = smem_u32(&vbuf[0][s]);
    const uint32_t slot1 = smem_u32(&vbuf[1][s]);

    // prefetch pot for t = 1
    float4 pA = *(const float4*)(prow + (size_t)S * S + c0);
    float4 pB = *(const float4*)(prow + (size_t)S * S + c1);

    for (int t = 1; t < T; ++t) {
        // prefetch for t+1 (lands during barrier/compute)
        const size_t nxt = (size_t)((t + 1 < T) ? (t + 1) : t) * S * S;
        float4 nA = *(const float4*)(prow + nxt + c0);
        float4 nB = *(const float4*)(prow + nxt + c1);

        // read v_{t-1} from LOCAL smem
        const float* vp = vbuf[(t - 1) & 1];
        float4 vA = *(const float4*)(vp + c0);
        float4 vB = *(const float4*)(vp + c1);

        // exps start immediately (K-shift: no max dependency)
        float e = __expf(vA.x + pA.x - K) + __expf(vA.y + pA.y - K) +
                  __expf(vA.z + pA.z - K) + __expf(vA.w + pA.w - K) +
                  __expf(vB.x + pB.x - K) + __expf(vB.y + pB.y - K) +
                  __expf(vB.z + pB.z - K) + __expf(vB.w + pB.w - K);

        // sum-only tree
        #pragma unroll
        for (int o = 16; o; o >>= 1)
            e += __shfl_xor_sync(0xffffffffu, e, o);

        float v = K + __logf(e);      // all lanes have v

        // publish v_t[s] into all 8 CTAs' smem (lanes 0..7, one rank each)
        const uint32_t dst = (t & 1) ? slot1 : slot0;
        if (lane < NCTA) {
            uint32_t rem;
            asm("mapa.shared::cluster.u32 %0, %1, %2;"
                : "=r"(rem) : "r"(dst), "r"(lane));
            asm volatile("st.shared::cluster.f32 [%0], %1;"
                         :: "r"(rem), "f"(v) : "memory");
        }
        asm volatile("barrier.cluster.arrive.aligned;" ::: "memory");

        // between arrive and wait: global v store
        if (lane == 0) vout[(size_t)t * S + s] = v;

        K = v;
        pA = nA; pB = nB;

        asm volatile("barrier.cluster.wait.aligned;" ::: "memory");
    }
}

// ============ parallel backpointer recompute ============
// bp[t][s] = argmax_{s'} (v[t-1][s'] + pot[t][s][s']), first-index tie-break
__global__ __launch_bounds__(256, 4)
void sv_bp(const float* __restrict__ pot, const float* __restrict__ out) {
    __shared__ float vprev[S];
    const int t    = (int)blockIdx.x + 1;
    const int tid  = threadIdx.x;
    const int w    = tid >> 5;
    const int lane = tid & 31;
    const float* vout = out + T;

    if (tid < S)
        vprev[tid] = (t == 1) ? pot[tid] : vout[(size_t)(t - 1) * S + tid];
    __syncthreads();

    const int c0 = 4 * lane;
    const int c1 = 128 + 4 * lane;
    float4 vA = *(const float4*)(vprev + c0);
    float4 vB = *(const float4*)(vprev + c1);

    // each warp handles 32 rows: s = w*32 + r
    for (int r = 0; r < 32; ++r) {
        const int s = w * 32 + r;
        const float* prow = pot + (size_t)t * S * S + (size_t)s * S;
        float4 pA = *(const float4*)(prow + c0);
        float4 pB = *(const float4*)(prow + c1);

        float sc[8];
        sc[0] = vA.x + pA.x;  sc[1] = vA.y + pA.y;
        sc[2] = vA.z + pA.z;  sc[3] = vA.w + pA.w;
        sc[4] = vB.x + pB.x;  sc[5] = vB.y + pB.y;
        sc[6] = vB.z + pB.z;  sc[7] = vB.w + pB.w;

        float m = sc[0]; int mi = c0;
        #pragma unroll
        for (int k = 1; k < 8; ++k) {
            int c = (k < 4) ? (c0 + k) : (c1 + (k - 4));
            if (sc[k] > m) { m = sc[k]; mi = c; }
        }
        #pragma unroll
        for (int o = 16; o; o >>= 1) {
            float om = __shfl_xor_sync(0xffffffffu, m, o);
            int   oi = __shfl_xor_sync(0xffffffffu, mi, o);
            if (om > m || (om == m && oi < mi)) { m = om; mi = oi; }
        }
        if (lane == 0) g_bp[t * S + s] = mi;
    }
}

// compose each chunk's backpointer map
__global__ void sv_link() {
    int b = blockIdx.x;
    if (b == 0) return;
    int cur = threadIdx.x;
    int tlo = b * CH;
    for (int t = tlo + CH - 2; t >= tlo - 1; --t)
        cur = g_bp[(t + 1) * S + cur];
    g_link[b][threadIdx.x] = cur;
}

__global__ void sv_back(float* __restrict__ out) {
    __shared__ float sm[8];
    __shared__ int   si[8];
    __shared__ int   sE[NB];
    const int tid = threadIdx.x, lane = tid & 31;

    const float* vlast = out + T + (size_t)(T - 1) * S;
    float m = vlast[tid]; int mi = tid;
    #pragma unroll
    for (int o = 16; o; o >>= 1) {
        float om = __shfl_xor_sync(0xffffffffu, m, o);
        int   oi = __shfl_xor_sync(0xffffffffu, mi, o);
        if (om > m || (om == m && oi < mi)) { m = om; mi = oi; }
    }
    if (lane == 0) { sm[tid >> 5] = m; si[tid >> 5] = mi; }
    __syncthreads();

    if (tid == 0) {
        m = sm[0]; mi = si[0];
        #pragma unroll
        for (int w = 1; w < 8; ++w)
            if (sm[w] > m || (sm[w] == m && si[w] < mi)) { m = sm[w]; mi = si[w]; }
        int e = mi;
        sE[NB - 1] = e;
        for (int b = NB - 1; b >= 1; --b) { e = g_link[b][e]; sE[b - 1] = e; }
    }
    __syncthreads();

    if (tid < NB) {
        int b = tid;
        int cur = sE[b];
        out[b * CH + CH - 1] = (float)cur;
        for (int t = b * CH + CH - 2; t >= b * CH; --t) {
            cur = g_bp[(t + 1) * S + cur];
            out[t] = (float)cur;
        }
    }
}

extern "C" void kernel_launch(void* const* d_in, const int* in_sizes, int n_in,
                              void* d_out, int out_size) {
    const float* pot = (const float*)d_in[0];
    float* out = (float*)d_out;

    sv_dp<<<NCTA, 1024>>>(pot, out);
    sv_bp<<<T - 1, 256>>>(pot, out);
    sv_link<<<NB, 256>>>();
    sv_back<<<1, 256>>>(out);
}

// round 8
// speedup vs baseline: 4.4035x; 1.0107x over previous
#include <cuda_runtime.h>
#include <math.h>
#include <cstdint>

#define T    4096
#define S    256
#define NCTA 16       // non-portable cluster size (fits in one GPC on B300)
#define WPC  16       // warps per CTA -> NCTA*WPC == S rows
#define NB   64       // backtrace chunks
#define CH   64       // steps per chunk (NB*CH == T)

// ---- device scratch (no cudaMalloc allowed) ----
__device__ int g_bp[T * S];       // backpointers (filled by sv_bp post-pass)
__device__ int g_link[NB][S];     // composed chunk maps

__device__ __forceinline__ uint32_t smem_u32(const void* p) {
    uint32_t a;
    asm("{ .reg .u64 t; cvta.to.shared.u64 t, %1; cvt.u32.u64 %0, t; }"
        : "=r"(a) : "l"(p));
    return a;
}
__device__ __forceinline__ uint32_t ctarank() {
    uint32_t r;
    asm("mov.u32 %0, %%cluster_ctarank;" : "=r"(r));
    return r;
}

// ============ sequential DP: LSE only, no argmax ============
__global__ __launch_bounds__(512, 1) __cluster_dims__(NCTA, 1, 1)
void sv_dp(const float* __restrict__ pot, float* __restrict__ out) {
    __shared__ float vbuf[2][S];      // double-buffered v, full copy per CTA

    const int tid  = threadIdx.x;
    const int w    = tid >> 5;
    const int lane = tid & 31;
    const uint32_t rank = ctarank();
    const int s    = (int)rank * WPC + w;       // state row owned by this warp
    float* vout = out + T;                      // v[t*S + s]

    // v0 = pot[0,0,:]: every CTA fills its local copy; CTA 0 also writes output
    if (tid < S) {
        vbuf[0][tid] = pot[tid];
        if (rank == 0) vout[tid] = pot[tid];
    }
    __syncthreads();

    const float* prow = pot + (size_t)s * S;
    const int c0 = 4 * lane;          // columns c0..c0+3
    const int c1 = 128 + 4 * lane;    // columns c1..c1+3

    float K = pot[s];                 // K-shift base (own previous v)

    const uint32_t slot0 = smem_u32(&vbuf[0][s]);
    const uint32_t slot1 = smem_u32(&vbuf[1][s]);

    // prefetch pot for t = 1
    float4 pA = *(const float4*)(prow + (size_t)S * S + c0);
    float4 pB = *(const float4*)(prow + (size_t)S * S + c1);

    for (int t = 1; t < T; ++t) {
        // prefetch for t+1 (lands during barrier/compute)
        const size_t nxt = (size_t)((t + 1 < T) ? (t + 1) : t) * S * S;
        float4 nA = *(const float4*)(prow + nxt + c0);
        float4 nB = *(const float4*)(prow + nxt + c1);

        // read v_{t-1} from LOCAL smem
        const float* vp = vbuf[(t - 1) & 1];
        float4 vA = *(const float4*)(vp + c0);
        float4 vB = *(const float4*)(vp + c1);

        // exps start immediately (K-shift: no max dependency)
        float e = __expf(vA.x + pA.x - K) + __expf(vA.y + pA.y - K) +
                  __expf(vA.z + pA.z - K) + __expf(vA.w + pA.w - K) +
                  __expf(vB.x + pB.x - K) + __expf(vB.y + pB.y - K) +
                  __expf(vB.z + pB.z - K) + __expf(vB.w + pB.w - K);

        // sum-only tree
        #pragma unroll
        for (int o = 16; o; o >>= 1)
            e += __shfl_xor_sync(0xffffffffu, e, o);

        float v = K + __logf(e);      // all lanes have v

        // publish v_t[s] into all 16 CTAs' smem (lanes 0..15, one rank each)
        const uint32_t dst = (t & 1) ? slot1 : slot0;
        if (lane < NCTA) {
            uint32_t rem;
            asm("mapa.shared::cluster.u32 %0, %1, %2;"
                : "=r"(rem) : "r"(dst), "r"(lane));
            asm volatile("st.shared::cluster.f32 [%0], %1;"
                         :: "r"(rem), "f"(v) : "memory");
        }
        asm volatile("barrier.cluster.arrive.aligned;" ::: "memory");

        // between arrive and wait: global v store
        if (lane == 0) vout[(size_t)t * S + s] = v;

        K = v;
        pA = nA; pB = nB;

        asm volatile("barrier.cluster.wait.aligned;" ::: "memory");
    }
}

// ============ parallel backpointer recompute ============
// bp[t][s] = argmax_{s'} (v[t-1][s'] + pot[t][s][s']), first-index tie-break
__global__ __launch_bounds__(256, 4)
void sv_bp(const float* __restrict__ pot, const float* __restrict__ out) {
    __shared__ float vprev[S];
    const int t    = (int)blockIdx.x + 1;
    const int tid  = threadIdx.x;
    const int w    = tid >> 5;
    const int lane = tid & 31;
    const float* vout = out + T;

    if (tid < S)
        vprev[tid] = (t == 1) ? pot[tid] : vout[(size_t)(t - 1) * S + tid];
    __syncthreads();

    const int c0 = 4 * lane;
    const int c1 = 128 + 4 * lane;
    float4 vA = *(const float4*)(vprev + c0);
    float4 vB = *(const float4*)(vprev + c1);

    // each warp handles 32 rows: s = w*32 + r
    for (int r = 0; r < 32; ++r) {
        const int s = w * 32 + r;
        const float* prow = pot + (size_t)t * S * S + (size_t)s * S;
        float4 pA = *(const float4*)(prow + c0);
        float4 pB = *(const float4*)(prow + c1);

        float sc[8];
        sc[0] = vA.x + pA.x;  sc[1] = vA.y + pA.y;
        sc[2] = vA.z + pA.z;  sc[3] = vA.w + pA.w;
        sc[4] = vB.x + pB.x;  sc[5] = vB.y + pB.y;
        sc[6] = vB.z + pB.z;  sc[7] = vB.w + pB.w;

        float m = sc[0]; int mi = c0;
        #pragma unroll
        for (int k = 1; k < 8; ++k) {
            int c = (k < 4) ? (c0 + k) : (c1 + (k - 4));
            if (sc[k] > m) { m = sc[k]; mi = c; }
        }
        #pragma unroll
        for (int o = 16; o; o >>= 1) {
            float om = __shfl_xor_sync(0xffffffffu, m, o);
            int   oi = __shfl_xor_sync(0xffffffffu, mi, o);
            if (om > m || (om == m && oi < mi)) { m = om; mi = oi; }
        }
        if (lane == 0) g_bp[t * S + s] = mi;
    }
}

// compose each chunk's backpointer map
__global__ void sv_link() {
    int b = blockIdx.x;
    if (b == 0) return;
    int cur = threadIdx.x;
    int tlo = b * CH;
    for (int t = tlo + CH - 2; t >= tlo - 1; --t)
        cur = g_bp[(t + 1) * S + cur];
    g_link[b][threadIdx.x] = cur;
}

__global__ void sv_back(float* __restrict__ out) {
    __shared__ float sm[8];
    __shared__ int   si[8];
    __shared__ int   sE[NB];
    const int tid = threadIdx.x, lane = tid & 31;

    const float* vlast = out + T + (size_t)(T - 1) * S;
    float m = vlast[tid]; int mi = tid;
    #pragma unroll
    for (int o = 16; o; o >>= 1) {
        float om = __shfl_xor_sync(0xffffffffu, m, o);
        int   oi = __shfl_xor_sync(0xffffffffu, mi, o);
        if (om > m || (om == m && oi < mi)) { m = om; mi = oi; }
    }
    if (lane == 0) { sm[tid >> 5] = m; si[tid >> 5] = mi; }
    __syncthreads();

    if (tid == 0) {
        m = sm[0]; mi = si[0];
        #pragma unroll
        for (int w = 1; w < 8; ++w)
            if (sm[w] > m || (sm[w] == m && si[w] < mi)) { m = sm[w]; mi = si[w]; }
        int e = mi;
        sE[NB - 1] = e;
        for (int b = NB - 1; b >= 1; --b) { e = g_link[b][e]; sE[b - 1] = e; }
    }
    __syncthreads();

    if (tid < NB) {
        int b = tid;
        int cur = sE[b];
        out[b * CH + CH - 1] = (float)cur;
        for (int t = b * CH + CH - 2; t >= b * CH; --t) {
            cur = g_bp[(t + 1) * S + cur];
            out[t] = (float)cur;
        }
    }
}

extern "C" void kernel_launch(void* const* d_in, const int* in_sizes, int n_in,
                              void* d_out, int out_size) {
    const float* pot = (const float*)d_in[0];
    float* out = (float*)d_out;

    // allow the 16-CTA non-portable cluster (idempotent, capture-legal)
    cudaFuncSetAttribute(sv_dp, cudaFuncAttributeNonPortableClusterSizeAllowed, 1);

    sv_dp<<<NCTA, 512>>>(pot, out);
    sv_bp<<<T - 1, 256>>>(pot, out);
    sv_link<<<NB, 256>>>();
    sv_back<<<1, 256>>>(out);
}